// round 3
// baseline (speedup 1.0000x reference)
#include <cuda_runtime.h>
#include <cuda_bf16.h>
#include <cstdint>

// ============================================================================
// FourierKernel: kernel[b,n,m] = (1/128) * sum_r f_r^2 * Re( X_r[b,n] conj(Y_r[b,m]) )
// with X = rfft(x)[:128]. Equivalent to phi @ psi^T where
//   phi = x @ U, psi = y @ U,
//   U[k, 2r]   =  cos(2*pi*r*k/512) * f_r / sqrt(128)
//   U[k, 2r+1] = -sin(2*pi*r*k/512) * f_r / sqrt(128)
//
// Stage 1: phi (16384x256) = x(16384x512) @ U(512x256)   [U stored transposed]
// Stage 2: out[b] (4096x4096) = phi[b] @ psi[b]^T, K=256, 4 batches
//
// GEMM: split-bf16 (a = a_hi + a_lo), fp32 acc, 3 mma passes (hihi, hilo, lohi).
// mma.sync.aligned.m16n8k16.row.col.f32.bf16.bf16.f32 + ldmatrix.
// CTA tile 128x128x32, 256 threads, 8 warps of 32x64.
// Register-staged pipeline: prefetch k-tile t+1 into regs during mma of tile t.
// ============================================================================

#define BATCH 4
#define SEQ   4096
#define FEAT  512
#define RANKC 256              // 2 * 128 modes
#define MTOT  (BATCH * SEQ)    // 16384

// scratch (device globals; no allocation allowed)
__device__ float g_Ut[RANKC * FEAT];     // [c][k], k contiguous (B operand)
__device__ float g_phi[MTOT * RANKC];
__device__ float g_psi[MTOT * RANKC];

// ---------------------------------------------------------------------------
// Basis generation: Ut[c*512 + k]
// ---------------------------------------------------------------------------
__global__ void gen_basis_kernel(const float* __restrict__ filt) {
    int idx = blockIdx.x * blockDim.x + threadIdx.x;   // 131072 total
    int c = idx >> 9;          // 0..255
    int k = idx & 511;         // 0..511
    int r = c >> 1;            // mode index 0..127
    float s = filt[r] * 0.08838834764831843f;          // 1/sqrt(128)
    int ph = (r * k) & 511;                            // exact mod 512
    float ang = (float)ph * 0.0122718463030851562f;    // 2*pi/512
    float sv, cv;
    sincosf(ang, &sv, &cv);
    g_Ut[idx] = (c & 1) ? (-sv * s) : (cv * s);
}

// ---------------------------------------------------------------------------
// helpers
// ---------------------------------------------------------------------------
static __device__ __forceinline__ uint32_t smem_u32(const void* p) {
    return (uint32_t)__cvta_generic_to_shared(p);
}

static __device__ __forceinline__ void ldm4(uint32_t& r0, uint32_t& r1,
                                            uint32_t& r2, uint32_t& r3,
                                            uint32_t addr) {
    asm volatile("ldmatrix.sync.aligned.m8n8.x4.shared.b16 {%0,%1,%2,%3}, [%4];"
                 : "=r"(r0), "=r"(r1), "=r"(r2), "=r"(r3) : "r"(addr));
}

static __device__ __forceinline__ void mma_bf16(float* c, const uint32_t* a,
                                                uint32_t b0, uint32_t b1) {
    asm volatile(
        "mma.sync.aligned.m16n8k16.row.col.f32.bf16.bf16.f32 "
        "{%0,%1,%2,%3},{%4,%5,%6,%7},{%8,%9},{%0,%1,%2,%3};"
        : "+f"(c[0]), "+f"(c[1]), "+f"(c[2]), "+f"(c[3])
        : "r"(a[0]), "r"(a[1]), "r"(a[2]), "r"(a[3]), "r"(b0), "r"(b1));
}

// fp32x4 -> (bf16 hi pair-packed, bf16 lo pair-packed); residual sub is exact.
static __device__ __forceinline__ void split4(float4 v, uint2& hi, uint2& lo) {
    __nv_bfloat162 h01 = __floats2bfloat162_rn(v.x, v.y);  // .x = low half (even k)
    __nv_bfloat162 h23 = __floats2bfloat162_rn(v.z, v.w);
    float rx = v.x - __bfloat162float(__low2bfloat16(h01));
    float ry = v.y - __bfloat162float(__high2bfloat16(h01));
    float rz = v.z - __bfloat162float(__low2bfloat16(h23));
    float rw = v.w - __bfloat162float(__high2bfloat16(h23));
    __nv_bfloat162 l01 = __floats2bfloat162_rn(rx, ry);
    __nv_bfloat162 l23 = __floats2bfloat162_rn(rz, rw);
    hi.x = *reinterpret_cast<uint32_t*>(&h01);
    hi.y = *reinterpret_cast<uint32_t*>(&h23);
    lo.x = *reinterpret_cast<uint32_t*>(&l01);
    lo.y = *reinterpret_cast<uint32_t*>(&l23);
}

// ---------------------------------------------------------------------------
// split-bf16 GEMM: C[bz] (128*gridY x 128*gridX) = A[bz] @ B[bz]^T
// A: row-major [M][lda] (k contiguous), B: row-major [N][ldb] (k contiguous).
// All dims divide tiles exactly (no guards): M%128==0, N%128==0, K%32==0.
// smem stride = 40 bf16 = 80 B (80*r mod 128 covers all 16B slots -> ldmatrix
// conflict-free).
// ---------------------------------------------------------------------------
__global__ __launch_bounds__(256)
void gemm_split_bf16(const float* __restrict__ A, const float* __restrict__ B,
                     float* __restrict__ C,
                     int lda, int ldb, int ldc, int K,
                     long long aStride, long long bStride, long long cStride) {
    __shared__ __align__(16) char sAhi[128 * 80];
    __shared__ __align__(16) char sAlo[128 * 80];
    __shared__ __align__(16) char sBhi[128 * 80];
    __shared__ __align__(16) char sBlo[128 * 80];

    const int tid   = threadIdx.x;
    const int lane  = tid & 31;
    const int warp  = tid >> 5;
    const int warpM = warp >> 1;    // 0..3  (32-row slices)
    const int warpN = warp & 1;     // 0..1  (64-col slices)
    const int group = lane >> 2;
    const int tig   = lane & 3;
    const int bz    = blockIdx.z;

    const float* Ab = A + (long long)bz * aStride + (long long)(blockIdx.y * 128) * lda;
    const float* Bb = B + (long long)bz * bStride + (long long)(blockIdx.x * 128) * ldb;

    // per-thread global-load coordinates (fixed across k-iterations)
    int rowA[4], c4A[4];
#pragma unroll
    for (int i = 0; i < 4; ++i) {
        int chunk = tid + i * 256;     // 1024 float4 chunks per 128x32 tile
        rowA[i] = chunk >> 3;          // 0..127
        c4A[i]  = chunk & 7;           // 0..7
    }

    float acc[2][8][4];
#pragma unroll
    for (int mt = 0; mt < 2; ++mt)
#pragma unroll
        for (int j = 0; j < 8; ++j)
#pragma unroll
            for (int q = 0; q < 4; ++q) acc[mt][j][q] = 0.0f;

    const uint32_t aBaseHi = smem_u32(sAhi);
    const uint32_t aBaseLo = smem_u32(sAlo);
    const uint32_t bBaseHi = smem_u32(sBhi);
    const uint32_t bBaseLo = smem_u32(sBlo);

    // ldmatrix.x4 lane addressing: lanes 0-15 -> rows base..base+15 (k bytes 0-15),
    // lanes 16-31 -> same rows, +16B.
    const int ldr   = lane & 15;
    const int ldoff = ((lane >> 4) << 4);

    // ---- prefetch k-tile 0 into registers ----
    float4 pa[4], pb[4];
#pragma unroll
    for (int i = 0; i < 4; ++i) {
        pa[i] = *reinterpret_cast<const float4*>(Ab + (long long)rowA[i] * lda + c4A[i] * 4);
        pb[i] = *reinterpret_cast<const float4*>(Bb + (long long)rowA[i] * ldb + c4A[i] * 4);
    }

    for (int kt = 0; kt < K; kt += 32) {
        // ---- split + store current registers to smem ----
#pragma unroll
        for (int i = 0; i < 4; ++i) {
            uint2 hi, lo;
            split4(pa[i], hi, lo);
            *reinterpret_cast<uint2*>(sAhi + rowA[i] * 80 + c4A[i] * 8) = hi;
            *reinterpret_cast<uint2*>(sAlo + rowA[i] * 80 + c4A[i] * 8) = lo;
            split4(pb[i], hi, lo);
            *reinterpret_cast<uint2*>(sBhi + rowA[i] * 80 + c4A[i] * 8) = hi;
            *reinterpret_cast<uint2*>(sBlo + rowA[i] * 80 + c4A[i] * 8) = lo;
        }
        __syncthreads();

        // ---- prefetch next k-tile while tensor pipe works on this one ----
        if (kt + 32 < K) {
            int kn = kt + 32;
#pragma unroll
            for (int i = 0; i < 4; ++i) {
                pa[i] = *reinterpret_cast<const float4*>(Ab + (long long)rowA[i] * lda + kn + c4A[i] * 4);
                pb[i] = *reinterpret_cast<const float4*>(Bb + (long long)rowA[i] * ldb + kn + c4A[i] * 4);
            }
        }

        // ---- two k16 steps of mma ----
#pragma unroll
        for (int s = 0; s < 2; ++s) {
            uint32_t aHi[2][4], aLo[2][4], bHi[8][2], bLo[8][2];
#pragma unroll
            for (int mt = 0; mt < 2; ++mt) {
                uint32_t off = (uint32_t)((warpM * 32 + mt * 16 + ldr) * 80 + s * 32 + ldoff);
                ldm4(aHi[mt][0], aHi[mt][1], aHi[mt][2], aHi[mt][3], aBaseHi + off);
                ldm4(aLo[mt][0], aLo[mt][1], aLo[mt][2], aLo[mt][3], aBaseLo + off);
            }
#pragma unroll
            for (int jp = 0; jp < 4; ++jp) {
                uint32_t off = (uint32_t)((warpN * 64 + jp * 16 + ldr) * 80 + s * 32 + ldoff);
                uint32_t t0, t1, t2, t3;
                ldm4(t0, t1, t2, t3, bBaseHi + off);
                bHi[2 * jp][0] = t0; bHi[2 * jp + 1][0] = t1;
                bHi[2 * jp][1] = t2; bHi[2 * jp + 1][1] = t3;
                ldm4(t0, t1, t2, t3, bBaseLo + off);
                bLo[2 * jp][0] = t0; bLo[2 * jp + 1][0] = t1;
                bLo[2 * jp][1] = t2; bLo[2 * jp + 1][1] = t3;
            }
#pragma unroll
            for (int mt = 0; mt < 2; ++mt)
#pragma unroll
                for (int j = 0; j < 8; ++j) {
                    mma_bf16(acc[mt][j], aHi[mt], bHi[j][0], bHi[j][1]);  // hi*hi
                    mma_bf16(acc[mt][j], aHi[mt], bLo[j][0], bLo[j][1]);  // hi*lo
                    mma_bf16(acc[mt][j], aLo[mt], bHi[j][0], bHi[j][1]);  // lo*hi
                }
        }
        __syncthreads();
    }

    // ---- epilogue: fp32 stores, float2 per fragment row ----
    float* Cb = C + (long long)bz * cStride;
#pragma unroll
    for (int mt = 0; mt < 2; ++mt)
#pragma unroll
        for (int j = 0; j < 8; ++j) {
            int r = blockIdx.y * 128 + warpM * 32 + mt * 16 + group;
            int c = blockIdx.x * 128 + warpN * 64 + j * 8 + tig * 2;
            float2 v0 = make_float2(acc[mt][j][0], acc[mt][j][1]);
            float2 v1 = make_float2(acc[mt][j][2], acc[mt][j][3]);
            *reinterpret_cast<float2*>(Cb + (long long)r * ldc + c) = v0;
            *reinterpret_cast<float2*>(Cb + (long long)(r + 8) * ldc + c) = v1;
        }
}

// ---------------------------------------------------------------------------
// launch
// ---------------------------------------------------------------------------
extern "C" void kernel_launch(void* const* d_in, const int* in_sizes, int n_in,
                              void* d_out, int out_size) {
    const float* x    = (const float*)d_in[0];   // (4, 4096, 512)
    const float* y    = (const float*)d_in[1];   // (4, 4096, 512)
    const float* filt = (const float*)d_in[2];   // (128,)
    float* out = (float*)d_out;                  // (4, 4096, 4096)

    float *dUt, *dPhi, *dPsi;
    cudaGetSymbolAddress((void**)&dUt,  g_Ut);   // host query, capture-safe
    cudaGetSymbolAddress((void**)&dPhi, g_phi);
    cudaGetSymbolAddress((void**)&dPsi, g_psi);

    // 1) basis
    gen_basis_kernel<<<512, 256>>>(filt);

    // 2) phi = x @ U, psi = y @ U    (M=16384, N=256, K=512)
    gemm_split_bf16<<<dim3(2, 128, 1), 256>>>(x, dUt, dPhi, 512, 512, 256, 512, 0, 0, 0);
    gemm_split_bf16<<<dim3(2, 128, 1), 256>>>(y, dUt, dPsi, 512, 512, 256, 512, 0, 0, 0);

    // 3) out[b] = phi[b] @ psi[b]^T  (M=N=4096, K=256, 4 batches)
    gemm_split_bf16<<<dim3(32, 32, 4), 256>>>(dPhi, dPsi, out,
                                              256, 256, 4096, 256,
                                              4096LL * 256, 4096LL * 256,
                                              4096LL * 4096);
}

// round 8
// speedup vs baseline: 1.0927x; 1.0927x over previous
#include <cuda_runtime.h>
#include <cuda_bf16.h>
#include <cstdint>

// ============================================================================
// FourierKernel via rank-256 factorization (legacy mma.sync path; harness
// compiles PTX for sm_100 base target -> tcgen05 unavailable).
//   phi = x @ U, psi = y @ U   (U = rfft basis * gaussian filter, rank 256)
//   out[b] = phi[b] @ psi[b]^T
//
// Split-bf16: v = hi + lo bf16 planes, fp32 acc, 3 passes (HH + HL + LH).
// phi/psi stored as PRE-SPLIT bf16 planes so stage 2 has zero convert math.
//
// GEMM kernel (templated):
//   CTA tile 128 x 256 x 32, 256 threads, 8 warps of 64x64.
//   cp.async double-buffered smem (2 x 60KB dynamic), 80B row stride
//   (16B-aligned, ldmatrix conflict-free).
//   Stage 1: SPLIT_A=1 (A fp32 split on load), OUT_SPLIT=1 -> phi/psi planes.
//            grid (1,128,2) z: x->phi, y->psi. M=16384,N=256,K=512.
//   Stage 2: SPLIT_A=0 (A bf16 planes), OUT_SPLIT=0 -> fp32 d_out.
//            grid (16,32,4) z=batch. M=N=4096, K=256.
// ============================================================================

#define SEQ   4096
#define BATCH 4
#define RANKC 256
#define FEAT  512
#define MTOT  (BATCH * SEQ)

__device__ __nv_bfloat16 g_UtH[RANKC * FEAT];
__device__ __nv_bfloat16 g_UtL[RANKC * FEAT];
__device__ __nv_bfloat16 g_phiH[MTOT * RANKC];
__device__ __nv_bfloat16 g_phiL[MTOT * RANKC];
__device__ __nv_bfloat16 g_psiH[MTOT * RANKC];
__device__ __nv_bfloat16 g_psiL[MTOT * RANKC];

// smem layout per buffer (80B row stride):
//   Ahi[128*80]=10240  Alo +10240  Bhi +20480 (256*80)  Blo +40960
#define BUF_BYTES 61440
#define A_LO_OFF  10240
#define B_HI_OFF  20480
#define B_LO_OFF  40960

// ---------------------------------------------------------------------------
static __device__ __forceinline__ uint32_t smem_u32(const void* p) {
    return (uint32_t)__cvta_generic_to_shared(p);
}
static __device__ __forceinline__ void ldm4(uint32_t& r0, uint32_t& r1,
                                            uint32_t& r2, uint32_t& r3,
                                            uint32_t addr) {
    asm volatile("ldmatrix.sync.aligned.m8n8.x4.shared.b16 {%0,%1,%2,%3}, [%4];"
                 : "=r"(r0), "=r"(r1), "=r"(r2), "=r"(r3) : "r"(addr));
}
static __device__ __forceinline__ void mma_bf16(float* c, const uint32_t* a,
                                                uint32_t b0, uint32_t b1) {
    asm volatile(
        "mma.sync.aligned.m16n8k16.row.col.f32.bf16.bf16.f32 "
        "{%0,%1,%2,%3},{%4,%5,%6,%7},{%8,%9},{%0,%1,%2,%3};"
        : "+f"(c[0]), "+f"(c[1]), "+f"(c[2]), "+f"(c[3])
        : "r"(a[0]), "r"(a[1]), "r"(a[2]), "r"(a[3]), "r"(b0), "r"(b1));
}
static __device__ __forceinline__ void cp16(uint32_t dst, const void* src) {
    asm volatile("cp.async.cg.shared.global [%0], [%1], 16;"
                 :: "r"(dst), "l"(src) : "memory");
}
#define CP_COMMIT() asm volatile("cp.async.commit_group;" ::: "memory")

// fp32x4 -> bf16 hi/lo packed pairs
static __device__ __forceinline__ void split4(float4 v, uint2& hi, uint2& lo) {
    __nv_bfloat162 h01 = __floats2bfloat162_rn(v.x, v.y);
    __nv_bfloat162 h23 = __floats2bfloat162_rn(v.z, v.w);
    float rx = v.x - __bfloat162float(__low2bfloat16(h01));
    float ry = v.y - __bfloat162float(__high2bfloat16(h01));
    float rz = v.z - __bfloat162float(__low2bfloat16(h23));
    float rw = v.w - __bfloat162float(__high2bfloat16(h23));
    __nv_bfloat162 l01 = __floats2bfloat162_rn(rx, ry);
    __nv_bfloat162 l23 = __floats2bfloat162_rn(rz, rw);
    hi.x = *reinterpret_cast<uint32_t*>(&h01);
    hi.y = *reinterpret_cast<uint32_t*>(&h23);
    lo.x = *reinterpret_cast<uint32_t*>(&l01);
    lo.y = *reinterpret_cast<uint32_t*>(&l23);
}

// ---------------------------------------------------------------------------
// Basis planes
// ---------------------------------------------------------------------------
__global__ void gen_basis_kernel(const float* __restrict__ filt) {
    int idx = blockIdx.x * blockDim.x + threadIdx.x;   // 131072
    int c = idx >> 9, k = idx & 511, r = c >> 1;
    float s = filt[r] * 0.08838834764831843f;          // 1/sqrt(128)
    float ang = (float)((r * k) & 511) * 0.0122718463030851562f;  // 2*pi/512
    float sv, cv;
    sincosf(ang, &sv, &cv);
    float u = (c & 1) ? (-sv * s) : (cv * s);
    __nv_bfloat16 h = __float2bfloat16_rn(u);
    g_UtH[idx] = h;
    g_UtL[idx] = __float2bfloat16_rn(u - __bfloat162float(h));
}

// ---------------------------------------------------------------------------
// GEMM: C (128 x 256 per CTA) = A(128xK) @ B(256xK)^T, split-bf16 3-pass
// ---------------------------------------------------------------------------
template <bool SPLIT_A, bool OUT_SPLIT>
__global__ __launch_bounds__(256, 1) void gemm_planes(
    const float* __restrict__ Af0, const float* __restrict__ Af1,
    const __nv_bfloat16* __restrict__ AH, const __nv_bfloat16* __restrict__ AL,
    const __nv_bfloat16* __restrict__ BH, const __nv_bfloat16* __restrict__ BL,
    float* __restrict__ Cf,
    __nv_bfloat16* __restrict__ CH0, __nv_bfloat16* __restrict__ CL0,
    __nv_bfloat16* __restrict__ CH1, __nv_bfloat16* __restrict__ CL1,
    int lda, int ldb, int ldc, int K) {
    extern __shared__ __align__(16) char dyn[];
    const uint32_t smemB = smem_u32(dyn);

    const int tid  = threadIdx.x, lane = tid & 31, wid = tid >> 5;
    const int warpM = wid >> 2;          // 0..1  (64-row slices)
    const int warpN = wid & 3;           // 0..3  (64-col slices)
    const int group = lane >> 2;         // 0..7
    const int tig   = lane & 3;          // 0..3
    const int z = blockIdx.z;

    const float* Afp = nullptr;
    long long aRow0, bRow0;
    if constexpr (SPLIT_A) {
        Afp = z ? Af1 : Af0;
        aRow0 = (long long)blockIdx.y * 128;
        bRow0 = 0;
    } else {
        aRow0 = (long long)z * SEQ + (long long)blockIdx.y * 128;
        bRow0 = (long long)z * SEQ + (long long)blockIdx.x * 256;
    }

    // ---- tile loader (A: sync split or async planes; B: async planes) ----
    auto load_tile = [&](int kt, int buf) {
        const int k0 = kt << 5;
        const uint32_t base = smemB + buf * BUF_BYTES;
        if constexpr (SPLIT_A) {
#pragma unroll
            for (int i = 0; i < 4; ++i) {
                int idx = tid + i * 256;       // 1024 float4
                int row = idx >> 3, v = idx & 7;
                float4 va = *reinterpret_cast<const float4*>(
                    Afp + (aRow0 + row) * lda + k0 + v * 4);
                uint2 hi, lo;
                split4(va, hi, lo);
                uint32_t o = base + row * 80 + v * 8;
                asm volatile("st.shared.v2.b32 [%0], {%1,%2};"
                             :: "r"(o), "r"(hi.x), "r"(hi.y) : "memory");
                asm volatile("st.shared.v2.b32 [%0], {%1,%2};"
                             :: "r"(o + A_LO_OFF), "r"(lo.x), "r"(lo.y) : "memory");
            }
        } else {
#pragma unroll
            for (int i = 0; i < 4; ++i) {
                int idx = tid + i * 256;       // 1024 chunks (2 planes x 128r x 4)
                int pl = idx >> 9, rem = idx & 511;
                int r = rem >> 2, c = rem & 3;
                const __nv_bfloat16* src =
                    (pl ? AL : AH) + (aRow0 + r) * lda + k0 + c * 8;
                cp16(base + pl * A_LO_OFF + r * 80 + c * 16, src);
            }
        }
#pragma unroll
        for (int i = 0; i < 8; ++i) {
            int idx = tid + i * 256;           // 2048 chunks (2 planes x 256r x 4)
            int pl = idx >> 10, rem = idx & 1023;
            int r = rem >> 2, c = rem & 3;
            const __nv_bfloat16* src =
                (pl ? BL : BH) + (bRow0 + r) * ldb + k0 + c * 8;
            cp16(base + B_HI_OFF + pl * 20480 + r * 80 + c * 16, src);
        }
        CP_COMMIT();
    };

    float acc[4][8][4];
#pragma unroll
    for (int mt = 0; mt < 4; ++mt)
#pragma unroll
        for (int j = 0; j < 8; ++j)
#pragma unroll
            for (int q = 0; q < 4; ++q) acc[mt][j][q] = 0.0f;

    const int ldr   = lane & 15;
    const int ldoff = ((lane >> 4) << 4);
    const int nT = K >> 5;

    load_tile(0, 0);

    for (int kt = 0; kt < nT; ++kt) {
        const int buf = kt & 1;
        if (kt + 1 < nT) {
            load_tile(kt + 1, buf ^ 1);
            asm volatile("cp.async.wait_group 1;" ::: "memory");
        } else {
            asm volatile("cp.async.wait_group 0;" ::: "memory");
        }
        __syncthreads();

        const uint32_t aHi = smemB + buf * BUF_BYTES;
        const uint32_t aLo = aHi + A_LO_OFF;
        const uint32_t bHi = aHi + B_HI_OFF;
        const uint32_t bLo = aHi + B_LO_OFF;

#pragma unroll
        for (int s = 0; s < 2; ++s) {
            uint32_t aH[4][4], aL[4][4], bH[8][2], bL[8][2];
#pragma unroll
            for (int mt = 0; mt < 4; ++mt) {
                uint32_t off = (uint32_t)((warpM * 64 + mt * 16 + ldr) * 80 + s * 32 + ldoff);
                ldm4(aH[mt][0], aH[mt][1], aH[mt][2], aH[mt][3], aHi + off);
                ldm4(aL[mt][0], aL[mt][1], aL[mt][2], aL[mt][3], aLo + off);
            }
#pragma unroll
            for (int jp = 0; jp < 4; ++jp) {
                uint32_t off = (uint32_t)((warpN * 64 + jp * 16 + ldr) * 80 + s * 32 + ldoff);
                uint32_t t0, t1, t2, t3;
                ldm4(t0, t1, t2, t3, bHi + off);
                bH[2 * jp][0] = t0; bH[2 * jp + 1][0] = t1;
                bH[2 * jp][1] = t2; bH[2 * jp + 1][1] = t3;
                ldm4(t0, t1, t2, t3, bLo + off);
                bL[2 * jp][0] = t0; bL[2 * jp + 1][0] = t1;
                bL[2 * jp][1] = t2; bL[2 * jp + 1][1] = t3;
            }
#pragma unroll
            for (int mt = 0; mt < 4; ++mt)
#pragma unroll
                for (int j = 0; j < 8; ++j) {
                    mma_bf16(acc[mt][j], aH[mt], bH[j][0], bH[j][1]);  // hi*hi
                    mma_bf16(acc[mt][j], aH[mt], bL[j][0], bL[j][1]);  // hi*lo
                    mma_bf16(acc[mt][j], aL[mt], bH[j][0], bH[j][1]);  // lo*hi
                }
        }
        __syncthreads();
    }

    // ---- epilogue ----
    if constexpr (!OUT_SPLIT) {
        float* Cb = Cf + (long long)z * SEQ * (long long)ldc;
#pragma unroll
        for (int mt = 0; mt < 4; ++mt)
#pragma unroll
            for (int j = 0; j < 8; ++j) {
                int r = blockIdx.y * 128 + warpM * 64 + mt * 16 + group;
                int c = blockIdx.x * 256 + warpN * 64 + j * 8 + tig * 2;
                *reinterpret_cast<float2*>(Cb + (long long)r * ldc + c) =
                    make_float2(acc[mt][j][0], acc[mt][j][1]);
                *reinterpret_cast<float2*>(Cb + (long long)(r + 8) * ldc + c) =
                    make_float2(acc[mt][j][2], acc[mt][j][3]);
            }
    } else {
        __nv_bfloat16* cH = z ? CH1 : CH0;
        __nv_bfloat16* cL = z ? CL1 : CL0;
#pragma unroll
        for (int mt = 0; mt < 4; ++mt)
#pragma unroll
            for (int j = 0; j < 8; ++j) {
                int r = blockIdx.y * 128 + warpM * 64 + mt * 16 + group;
                int c = warpN * 64 + j * 8 + tig * 2;
#pragma unroll
                for (int half = 0; half < 2; ++half) {
                    float f0 = acc[mt][j][2 * half];
                    float f1 = acc[mt][j][2 * half + 1];
                    __nv_bfloat162 hp = __floats2bfloat162_rn(f0, f1);
                    float l0 = f0 - __bfloat162float(__low2bfloat16(hp));
                    float l1 = f1 - __bfloat162float(__high2bfloat16(hp));
                    __nv_bfloat162 lp = __floats2bfloat162_rn(l0, l1);
                    size_t go = (size_t)(r + half * 8) * (size_t)ldc + c;
                    *reinterpret_cast<uint32_t*>(cH + go) =
                        *reinterpret_cast<uint32_t*>(&hp);
                    *reinterpret_cast<uint32_t*>(cL + go) =
                        *reinterpret_cast<uint32_t*>(&lp);
                }
            }
    }
}

// ---------------------------------------------------------------------------
// launch
// ---------------------------------------------------------------------------
extern "C" void kernel_launch(void* const* d_in, const int* in_sizes, int n_in,
                              void* d_out, int out_size) {
    const float* x    = (const float*)d_in[0];   // (4, 4096, 512)
    const float* y    = (const float*)d_in[1];   // (4, 4096, 512)
    const float* filt = (const float*)d_in[2];   // (128,)
    float* out = (float*)d_out;                  // (4, 4096, 4096)

    __nv_bfloat16 *utH, *utL, *phH, *phL, *psH, *psL;
    cudaGetSymbolAddress((void**)&utH, g_UtH);
    cudaGetSymbolAddress((void**)&utL, g_UtL);
    cudaGetSymbolAddress((void**)&phH, g_phiH);
    cudaGetSymbolAddress((void**)&phL, g_phiL);
    cudaGetSymbolAddress((void**)&psH, g_psiH);
    cudaGetSymbolAddress((void**)&psL, g_psiL);

    const int SMEM = 2 * BUF_BYTES;   // 122880
    cudaFuncSetAttribute(gemm_planes<true, true>,
                         cudaFuncAttributeMaxDynamicSharedMemorySize, SMEM);
    cudaFuncSetAttribute(gemm_planes<false, false>,
                         cudaFuncAttributeMaxDynamicSharedMemorySize, SMEM);

    // 1) basis planes
    gen_basis_kernel<<<512, 256>>>(filt);

    // 2) phi/psi planes: z=0 -> x, z=1 -> y.  M=16384, N=256, K=512
    gemm_planes<true, true><<<dim3(1, 128, 2), 256, SMEM>>>(
        x, y, nullptr, nullptr, utH, utL,
        nullptr, phH, phL, psH, psL,
        FEAT, FEAT, RANKC, FEAT);

    // 3) out[b] = phi[b] @ psi[b]^T.  M=N=4096, K=256, z=batch
    gemm_planes<false, false><<<dim3(16, 32, 4), 256, SMEM>>>(
        nullptr, nullptr, phH, phL, psH, psL,
        out, nullptr, nullptr, nullptr, nullptr,
        RANKC, RANKC, SEQ, RANKC);
}

// round 10
// speedup vs baseline: 1.2429x; 1.1374x over previous
#include <cuda_runtime.h>
#include <cuda_bf16.h>
#include <cstdint>

// ============================================================================
// FourierKernel via rank-256 factorization (legacy mma.sync; harness targets
// sm_100 base so tcgen05 is unavailable).
//   phi = x @ U, psi = y @ U    (U = rfft basis * gaussian filter, rank 256)
//   out[b] = phi[b] @ psi[b]^T
// Split-bf16: v = hi + lo planes, fp32 acc, 3 passes (HH + HL + LH).
// phi/psi stored PRE-SPLIT so stage 2 has zero convert math.
//
// GEMM: CTA tile 128x128x32, 256 thr, 8 warps of 32x64, TWO CTAs PER SM
// (regs <= 128 via per-pair B fragment loading, smem 80KB/CTA), cp.async
// double buffer, ONE __syncthreads per k-iteration.
//   Stage 1: SPLIT_A=1, OUT_SPLIT=1, grid (2,128,2)  M=16384,N=256,K=512
//   Stage 2: SPLIT_A=0, OUT_SPLIT=0, grid (32,32,4)  M=N=4096,K=256
// ============================================================================

#define SEQ   4096
#define BATCH 4
#define RANKC 256
#define FEAT  512
#define MTOT  (BATCH * SEQ)

__device__ __nv_bfloat16 g_UtH[RANKC * FEAT];
__device__ __nv_bfloat16 g_UtL[RANKC * FEAT];
__device__ __nv_bfloat16 g_phiH[MTOT * RANKC];
__device__ __nv_bfloat16 g_phiL[MTOT * RANKC];
__device__ __nv_bfloat16 g_psiH[MTOT * RANKC];
__device__ __nv_bfloat16 g_psiL[MTOT * RANKC];

// per-buffer smem (80B row stride): Ahi[128*80] Alo Bhi Blo
#define A_LO_OFF  10240
#define B_HI_OFF  20480
#define B_LO_OFF  30720
#define BUF_BYTES 40960

// ---------------------------------------------------------------------------
static __device__ __forceinline__ uint32_t smem_u32(const void* p) {
    return (uint32_t)__cvta_generic_to_shared(p);
}
static __device__ __forceinline__ void ldm4(uint32_t& r0, uint32_t& r1,
                                            uint32_t& r2, uint32_t& r3,
                                            uint32_t addr) {
    asm volatile("ldmatrix.sync.aligned.m8n8.x4.shared.b16 {%0,%1,%2,%3}, [%4];"
                 : "=r"(r0), "=r"(r1), "=r"(r2), "=r"(r3) : "r"(addr));
}
static __device__ __forceinline__ void mma_bf16(float* c, const uint32_t* a,
                                                uint32_t b0, uint32_t b1) {
    asm volatile(
        "mma.sync.aligned.m16n8k16.row.col.f32.bf16.bf16.f32 "
        "{%0,%1,%2,%3},{%4,%5,%6,%7},{%8,%9},{%0,%1,%2,%3};"
        : "+f"(c[0]), "+f"(c[1]), "+f"(c[2]), "+f"(c[3])
        : "r"(a[0]), "r"(a[1]), "r"(a[2]), "r"(a[3]), "r"(b0), "r"(b1));
}
static __device__ __forceinline__ void cp16(uint32_t dst, const void* src) {
    asm volatile("cp.async.cg.shared.global [%0], [%1], 16;"
                 :: "r"(dst), "l"(src) : "memory");
}
#define CP_COMMIT() asm volatile("cp.async.commit_group;" ::: "memory")
#define CP_WAIT0()  asm volatile("cp.async.wait_group 0;" ::: "memory")

static __device__ __forceinline__ void split4(float4 v, uint2& hi, uint2& lo) {
    __nv_bfloat162 h01 = __floats2bfloat162_rn(v.x, v.y);
    __nv_bfloat162 h23 = __floats2bfloat162_rn(v.z, v.w);
    float rx = v.x - __bfloat162float(__low2bfloat16(h01));
    float ry = v.y - __bfloat162float(__high2bfloat16(h01));
    float rz = v.z - __bfloat162float(__low2bfloat16(h23));
    float rw = v.w - __bfloat162float(__high2bfloat16(h23));
    __nv_bfloat162 l01 = __floats2bfloat162_rn(rx, ry);
    __nv_bfloat162 l23 = __floats2bfloat162_rn(rz, rw);
    hi.x = *reinterpret_cast<uint32_t*>(&h01);
    hi.y = *reinterpret_cast<uint32_t*>(&h23);
    lo.x = *reinterpret_cast<uint32_t*>(&l01);
    lo.y = *reinterpret_cast<uint32_t*>(&l23);
}

// ---------------------------------------------------------------------------
__global__ void gen_basis_kernel(const float* __restrict__ filt) {
    int idx = blockIdx.x * blockDim.x + threadIdx.x;   // 131072
    int c = idx >> 9, k = idx & 511, r = c >> 1;
    float s = filt[r] * 0.08838834764831843f;          // 1/sqrt(128)
    float ang = (float)((r * k) & 511) * 0.0122718463030851562f;  // 2*pi/512
    float sv, cv;
    sincosf(ang, &sv, &cv);
    float u = (c & 1) ? (-sv * s) : (cv * s);
    __nv_bfloat16 h = __float2bfloat16_rn(u);
    g_UtH[idx] = h;
    g_UtL[idx] = __float2bfloat16_rn(u - __bfloat162float(h));
}

// ---------------------------------------------------------------------------
// GEMM: C (128x128 per CTA) = A(128xK) @ B(128xK)^T, split-bf16 3-pass
// ---------------------------------------------------------------------------
template <bool SPLIT_A, bool OUT_SPLIT>
__global__ __launch_bounds__(256, 2) void gemm_planes(
    const float* __restrict__ Af0, const float* __restrict__ Af1,
    const __nv_bfloat16* __restrict__ AH, const __nv_bfloat16* __restrict__ AL,
    const __nv_bfloat16* __restrict__ BH, const __nv_bfloat16* __restrict__ BL,
    float* __restrict__ Cf,
    __nv_bfloat16* __restrict__ CH0, __nv_bfloat16* __restrict__ CL0,
    __nv_bfloat16* __restrict__ CH1, __nv_bfloat16* __restrict__ CL1,
    int lda, int ldb, int ldc, int K) {
    extern __shared__ __align__(16) char dyn[];
    const uint32_t smemB = smem_u32(dyn);

    const int tid  = threadIdx.x, lane = tid & 31, wid = tid >> 5;
    const int warpM = wid >> 1;          // 0..3  (32-row slices)
    const int warpN = wid & 1;           // 0..1  (64-col slices)
    const int group = lane >> 2;         // 0..7
    const int tig   = lane & 3;          // 0..3
    const int z = blockIdx.z;

    const float* Afp = nullptr;
    long long aRow0, bRow0;
    if constexpr (SPLIT_A) {
        Afp = z ? Af1 : Af0;
        aRow0 = (long long)blockIdx.y * 128;
        bRow0 = (long long)blockIdx.x * 128;
    } else {
        aRow0 = (long long)z * SEQ + (long long)blockIdx.y * 128;
        bRow0 = (long long)z * SEQ + (long long)blockIdx.x * 128;
    }

    // ---- tile loader into buffer `buf` for k-tile kt ----
    auto load_tile = [&](int kt, int buf) {
        const int k0 = kt << 5;
        const uint32_t base = smemB + buf * BUF_BYTES;
        if constexpr (SPLIT_A) {
            // A fp32 128x32: 1024 float4, split in regs, STS hi/lo
#pragma unroll
            for (int i = 0; i < 4; ++i) {
                int idx = tid + i * 256;
                int row = idx >> 3, v = idx & 7;
                float4 va = *reinterpret_cast<const float4*>(
                    Afp + (aRow0 + row) * lda + k0 + v * 4);
                uint2 hi, lo;
                split4(va, hi, lo);
                uint32_t o = base + row * 80 + v * 8;
                asm volatile("st.shared.v2.b32 [%0], {%1,%2};"
                             :: "r"(o), "r"(hi.x), "r"(hi.y) : "memory");
                asm volatile("st.shared.v2.b32 [%0], {%1,%2};"
                             :: "r"(o + A_LO_OFF), "r"(lo.x), "r"(lo.y) : "memory");
            }
        } else {
            // A planes: 1024 16B chunks (2 planes x 128 rows x 4)
#pragma unroll
            for (int i = 0; i < 4; ++i) {
                int idx = tid + i * 256;
                int pl = idx >> 9, rem = idx & 511;
                int r = rem >> 2, c = rem & 3;
                const __nv_bfloat16* src =
                    (pl ? AL : AH) + (aRow0 + r) * lda + k0 + c * 8;
                cp16(base + pl * A_LO_OFF + r * 80 + c * 16, src);
            }
        }
        // B planes: 1024 16B chunks (2 planes x 128 rows x 4)
#pragma unroll
        for (int i = 0; i < 4; ++i) {
            int idx = tid + i * 256;
            int pl = idx >> 9, rem = idx & 511;
            int r = rem >> 2, c = rem & 3;
            const __nv_bfloat16* src =
                (pl ? BL : BH) + (bRow0 + r) * ldb + k0 + c * 8;
            cp16(base + B_HI_OFF + pl * 10240 + r * 80 + c * 16, src);
        }
        CP_COMMIT();
    };

    float acc[2][8][4];
#pragma unroll
    for (int mt = 0; mt < 2; ++mt)
#pragma unroll
        for (int j = 0; j < 8; ++j)
#pragma unroll
            for (int q = 0; q < 4; ++q) acc[mt][j][q] = 0.0f;

    const int ldr   = lane & 15;
    const int ldoff = ((lane >> 4) << 4);
    const int nT = K >> 5;

    load_tile(0, 0);

    for (int kt = 0; kt < nT; ++kt) {
        const int buf = kt & 1;
        CP_WAIT0();
        __syncthreads();
        // prefetch next tile into the other buffer; overlaps compute below
        if (kt + 1 < nT) load_tile(kt + 1, buf ^ 1);

        const uint32_t aHi = smemB + buf * BUF_BYTES;
        const uint32_t aLo = aHi + A_LO_OFF;
        const uint32_t bHi = aHi + B_HI_OFF;
        const uint32_t bLo = aHi + B_LO_OFF;

#pragma unroll
        for (int s = 0; s < 2; ++s) {
            uint32_t aH[2][4], aL[2][4];
#pragma unroll
            for (int mt = 0; mt < 2; ++mt) {
                uint32_t off = (uint32_t)((warpM * 32 + mt * 16 + ldr) * 80 + s * 32 + ldoff);
                ldm4(aH[mt][0], aH[mt][1], aH[mt][2], aH[mt][3], aHi + off);
                ldm4(aL[mt][0], aL[mt][1], aL[mt][2], aL[mt][3], aLo + off);
            }
#pragma unroll
            for (int jp = 0; jp < 4; ++jp) {
                uint32_t off = (uint32_t)((warpN * 64 + jp * 16 + ldr) * 80 + s * 32 + ldoff);
                uint32_t h0, h1, h2, h3, l0, l1, l2, l3;
                ldm4(h0, h1, h2, h3, bHi + off);
                ldm4(l0, l1, l2, l3, bLo + off);
#pragma unroll
                for (int mt = 0; mt < 2; ++mt) {
                    mma_bf16(acc[mt][2 * jp],     aH[mt], h0, h2);  // hi*hi
                    mma_bf16(acc[mt][2 * jp + 1], aH[mt], h1, h3);
                    mma_bf16(acc[mt][2 * jp],     aH[mt], l0, l2);  // hi*lo
                    mma_bf16(acc[mt][2 * jp + 1], aH[mt], l1, l3);
                    mma_bf16(acc[mt][2 * jp],     aL[mt], h0, h2);  // lo*hi
                    mma_bf16(acc[mt][2 * jp + 1], aL[mt], h1, h3);
                }
            }
        }
    }

    // ---- epilogue ----
    if constexpr (!OUT_SPLIT) {
        float* Cb = Cf + (long long)z * SEQ * (long long)ldc;
#pragma unroll
        for (int mt = 0; mt < 2; ++mt)
#pragma unroll
            for (int j = 0; j < 8; ++j) {
                int r = blockIdx.y * 128 + warpM * 32 + mt * 16 + group;
                int c = blockIdx.x * 128 + warpN * 64 + j * 8 + tig * 2;
                *reinterpret_cast<float2*>(Cb + (long long)r * ldc + c) =
                    make_float2(acc[mt][j][0], acc[mt][j][1]);
                *reinterpret_cast<float2*>(Cb + (long long)(r + 8) * ldc + c) =
                    make_float2(acc[mt][j][2], acc[mt][j][3]);
            }
    } else {
        __nv_bfloat16* cH = z ? CH1 : CH0;
        __nv_bfloat16* cL = z ? CL1 : CL0;
#pragma unroll
        for (int mt = 0; mt < 2; ++mt)
#pragma unroll
            for (int j = 0; j < 8; ++j) {
                int r = blockIdx.y * 128 + warpM * 32 + mt * 16 + group;
                int c = blockIdx.x * 128 + warpN * 64 + j * 8 + tig * 2;
#pragma unroll
                for (int half = 0; half < 2; ++half) {
                    float f0 = acc[mt][j][2 * half];
                    float f1 = acc[mt][j][2 * half + 1];
                    __nv_bfloat162 hp = __floats2bfloat162_rn(f0, f1);
                    float l0 = f0 - __bfloat162float(__low2bfloat16(hp));
                    float l1 = f1 - __bfloat162float(__high2bfloat16(hp));
                    __nv_bfloat162 lp = __floats2bfloat162_rn(l0, l1);
                    size_t go = (size_t)(r + half * 8) * (size_t)ldc + c;
                    *reinterpret_cast<uint32_t*>(cH + go) =
                        *reinterpret_cast<uint32_t*>(&hp);
                    *reinterpret_cast<uint32_t*>(cL + go) =
                        *reinterpret_cast<uint32_t*>(&lp);
                }
            }
    }
}

// ---------------------------------------------------------------------------
extern "C" void kernel_launch(void* const* d_in, const int* in_sizes, int n_in,
                              void* d_out, int out_size) {
    const float* x    = (const float*)d_in[0];   // (4, 4096, 512)
    const float* y    = (const float*)d_in[1];   // (4, 4096, 512)
    const float* filt = (const float*)d_in[2];   // (128,)
    float* out = (float*)d_out;                  // (4, 4096, 4096)

    __nv_bfloat16 *utH, *utL, *phH, *phL, *psH, *psL;
    cudaGetSymbolAddress((void**)&utH, g_UtH);
    cudaGetSymbolAddress((void**)&utL, g_UtL);
    cudaGetSymbolAddress((void**)&phH, g_phiH);
    cudaGetSymbolAddress((void**)&phL, g_phiL);
    cudaGetSymbolAddress((void**)&psH, g_psiH);
    cudaGetSymbolAddress((void**)&psL, g_psiL);

    const int SMEM = 2 * BUF_BYTES;   // 81920 -> 2 CTAs/SM
    cudaFuncSetAttribute(gemm_planes<true, true>,
                         cudaFuncAttributeMaxDynamicSharedMemorySize, SMEM);
    cudaFuncSetAttribute(gemm_planes<false, false>,
                         cudaFuncAttributeMaxDynamicSharedMemorySize, SMEM);

    // 1) basis planes
    gen_basis_kernel<<<512, 256>>>(filt);

    // 2) phi/psi planes: z=0 -> x, z=1 -> y.  M=16384, N=256, K=512
    gemm_planes<true, true><<<dim3(2, 128, 2), 256, SMEM>>>(
        x, y, nullptr, nullptr, utH, utL,
        nullptr, phH, phL, psH, psL,
        FEAT, FEAT, RANKC, FEAT);

    // 3) out[b] = phi[b] @ psi[b]^T.  M=N=4096, K=256, z=batch
    gemm_planes<false, false><<<dim3(32, 32, 4), 256, SMEM>>>(
        nullptr, nullptr, phH, phL, psH, psL,
        out, nullptr, nullptr, nullptr, nullptr,
        RANKC, RANKC, SEQ, RANKC);
}